// round 7
// baseline (speedup 1.0000x reference)
#include <cuda_runtime.h>

// Census loss, pair-symmetric, image-interleaved smem (float2 = {gx, gy}).
// total = sum_{unordered pairs (a,b), off in H(24)} t * (v(a)+v(b))
// t = 1 - 0.1*rc, rc = 1/(0.1+e^2), e = cx-cy, c = d*rsqrt(7.29+d^2),
// d = g3(b)-g3(a), g3 = r+g+b (the /3 is folded into 0.81*9=7.29).
// Interior: all weights == 2 -> per-pixel res = 48 - 0.2*sum(rc).

#define IMG   256
#define IMG2  65536
#define SW    38            // window row width in float2 (32 + 6 halo)
#define SROWS 14            // 8 tile rows + 6 halo
#define NELEM (SROWS * SW)  // 532

__device__ __forceinline__ float frsqrt_a(float x){ float r; asm("rsqrt.approx.f32 %0, %1;" : "=f"(r) : "f"(x)); return r; }
__device__ __forceinline__ float frcp_a  (float x){ float r; asm("rcp.approx.f32 %0, %1;"   : "=f"(r) : "f"(x)); return r; }

// rc = 1/(0.1+e^2) for one pair; nb/cen are (x-image, y-image) interleaved
__device__ __forceinline__ float pair_rc(float2 nb, float2 cen)
{
    float dX = nb.x - cen.x;
    float dY = nb.y - cen.y;
    float rX = frsqrt_a(fmaf(dX, dX, 7.29f));
    float rY = frsqrt_a(fmaf(dY, dY, 7.29f));
    float cY = dY * rY;
    float e  = fmaf(dX, rX, -cY);
    return frcp_a(fmaf(e, e, 0.1f));
}

template<bool BORDER>
__device__ __forceinline__ float census_px(const float2* __restrict__ base,
                                           int R, int C)
{
    float vrow[4], vcol[7], va;
    if (BORDER) {
#pragma unroll
        for (int d = 0; d < 4; d++) vrow[d] = ((unsigned)(R + d - 3) < 250u) ? 1.f : 0.f;
#pragma unroll
        for (int j = 0; j < 7; j++) vcol[j] = ((unsigned)(C + j - 6) < 250u) ? 1.f : 0.f;
        va = vrow[0] * vcol[3];
    }

    const float2 cen = base[3];
    float accA = 0.f, accB = 0.f;   // two chains for ILP
    float accw = 0.f;

    // dy = 0: dx = 1..3 (j = 4..6)
#pragma unroll
    for (int j = 4; j < 7; j++) {
        float rc = pair_rc(base[j], cen);
        if (BORDER) {
            float w = fmaf(vrow[0], vcol[j], va);
            accw += w;
            accA = fmaf(w, rc, accA);
        } else accA += rc;
    }

    // dy = 1..3: dx = -3..3 (j = 0..6)
#pragma unroll
    for (int dy = 1; dy < 4; dy++) {
        const float2* row = base + dy * SW;
#pragma unroll
        for (int j = 0; j < 7; j++) {
            float rc = pair_rc(row[j], cen);
            if (BORDER) {
                float w = fmaf(vrow[dy], vcol[j], va);
                accw += w;
                if (j & 1) accB = fmaf(w, rc, accB);
                else       accA = fmaf(w, rc, accA);
            } else {
                if (j & 1) accB += rc;
                else       accA += rc;
            }
        }
    }

    float s = accA + accB;
    // interior: 24 pairs, weight 2 each: 2*(24 - 0.1*sum_rc)
    return BORDER ? fmaf(-0.1f, s, accw) : fmaf(-0.2f, s, 48.f);
}

__global__ __launch_bounds__(256, 5)
void census_loss_kernel(const float* __restrict__ x,
                        const float* __restrict__ y,
                        float* __restrict__ out)
{
    __shared__ __align__(16) float2 sg[NELEM];

    const int b    = blockIdx.z;
    const int row0 = blockIdx.y * 8;
    const int col0 = blockIdx.x * 32;
    const int tid  = threadIdx.y * 32 + threadIdx.x;

    const float* xb = x + (size_t)b * 3 * IMG2;
    const float* yb = y + (size_t)b * 3 * IMG2;

    // interleaved 3*grayscale tile + halo (zeros outside; weight 0 kills them)
#pragma unroll
    for (int it = 0; it < 3; it++) {
        int i = tid + it * 256;
        if (i < NELEM) {
            int lr = i / SW;
            int lc = i - lr * SW;
            int gr = row0 - 3 + lr;
            int gc = col0 - 3 + lc;
            float gx = 0.f, gy = 0.f;
            if ((unsigned)gr < 256u && (unsigned)gc < 256u) {
                int o = gr * IMG + gc;
                gx = xb[o] + xb[o + IMG2] + xb[o + 2 * IMG2];
                gy = yb[o] + yb[o + IMG2] + yb[o + 2 * IMG2];
            }
            sg[i] = make_float2(gx, gy);
        }
    }
    __syncthreads();

    const int tx = threadIdx.x;          // 0..31 -> pixel col
    const int ty = threadIdx.y;          // 0..7  -> pixel row
    // window elem j at base[dy*SW + j], j = 0..6 <-> dx = j-3; center = base[3]
    const float2* base = sg + (ty + 3) * SW + tx;

    const int R = row0 + ty;
    const int C = col0 + tx;

    const bool interior = (blockIdx.x - 1u < 6u) & (blockIdx.y - 1u < 30u);

    float res = interior ? census_px<false>(base, R, C)
                         : census_px<true >(base, R, C);

    // warp + block reduction (8 warps)
#pragma unroll
    for (int s = 16; s > 0; s >>= 1)
        res += __shfl_xor_sync(0xFFFFFFFFu, res, s);

    __shared__ float wsum[8];
    if ((tid & 31) == 0) wsum[tid >> 5] = res;
    __syncthreads();
    if (tid < 8) {
        float v = wsum[tid];
        v += __shfl_xor_sync(0xFFu, v, 4);
        v += __shfl_xor_sync(0xFFu, v, 2);
        v += __shfl_xor_sync(0xFFu, v, 1);
        if (tid == 0)
            atomicAdd(out, v * (1.f / 25690112.f));   // 1/(49*8*256*256)
    }
}

extern "C" void kernel_launch(void* const* d_in, const int* in_sizes, int n_in,
                              void* d_out, int out_size)
{
    const float* x = (const float*)d_in[0];
    const float* y = (const float*)d_in[1];
    float* out = (float*)d_out;

    cudaMemsetAsync(out, 0, sizeof(float));

    dim3 block(32, 8, 1);
    dim3 grid(8, 32, 8);   // 2048 blocks, 1 pixel/thread
    census_loss_kernel<<<grid, block>>>(x, y, out);
}

// round 8
// speedup vs baseline: 1.5009x; 1.5009x over previous
#include <cuda_runtime.h>

// Census loss, pair-symmetric, f32x2-packed, 2 adjacent pixels/thread.
// total = sum_{unordered pairs, off in H(24)} t*(v(a)+v(b)),
// t = 1 - 0.1*rc, rc = 1/(0.1+e^2), e = cx-cy, c = d*rsqrt(7.29+d^2),
// d = g3(b)-g3(a), g3 = r+g+b (the /3 folded into 0.81*9 = 7.29).
// Interior thread (48 pairs, all weights 2): res = 96 - 0.2*sum(rc).
// Layout: pitch-40 smem rows, LEFT halo 4 -> center pixel pair is an aligned
// LDS.64; even-dx neighbor pairs are aligned LDS.64 (zero packing MOVs).

#define IMG   256
#define IMG2  65536
#define TCOLS 32
#define TROWS 16
#define SW    40   // padded pitch (floats): 4 left halo + 32 + 3 right + 1 pad
#define SWR   22   // TROWS + 6
#define SW2   20   // pitch in float2

typedef unsigned long long ull;

__device__ __forceinline__ float frsqrt_a(float x){ float r; asm("rsqrt.approx.f32 %0, %1;" : "=f"(r) : "f"(x)); return r; }
__device__ __forceinline__ float frcp_a  (float x){ float r; asm("rcp.approx.f32 %0, %1;"   : "=f"(r) : "f"(x)); return r; }

__device__ __forceinline__ ull pk(float lo, float hi){ ull r; asm("mov.b64 %0, {%1, %2};" : "=l"(r) : "f"(lo), "f"(hi)); return r; }
__device__ __forceinline__ float2 upk(ull v){ float2 f; asm("mov.b64 {%0, %1}, %2;" : "=f"(f.x), "=f"(f.y) : "l"(v)); return f; }
__device__ __forceinline__ ull fma2(ull a, ull b, ull c){ ull r; asm("fma.rn.f32x2 %0, %1, %2, %3;" : "=l"(r) : "l"(a), "l"(b), "l"(c)); return r; }
__device__ __forceinline__ ull mul2(ull a, ull b){ ull r; asm("mul.rn.f32x2 %0, %1, %2;" : "=l"(r) : "l"(a), "l"(b)); return r; }

__device__ __forceinline__ ull lds64(const float* p){
    ull r; asm("ld.shared.b64 %0, [%1];" : "=l"(r) : "l"((size_t)__cvta_generic_to_shared(p))); return r;
}

// packed rc = 1/(0.1+e^2) for two pixel-pairs
__device__ __forceinline__ float2 pair_rc2(ull nbx, ull nby, ull cenx, ull ceny,
                                           ull NEG1, ull C729, ull C01)
{
    ull dX = fma2(cenx, NEG1, nbx);          // nb - cen
    ull dY = fma2(ceny, NEG1, nby);
    ull aX = fma2(dX, dX, C729);
    ull aY = fma2(dY, dY, C729);
    float2 a = upk(aX);
    ull rX = pk(frsqrt_a(a.x), frsqrt_a(a.y));
    float2 b = upk(aY);
    ull rY = pk(frsqrt_a(b.x), frsqrt_a(b.y));
    ull cx = mul2(dX, rX);
    ull cy = mul2(dY, rY);
    ull e  = fma2(cy, NEG1, cx);             // cx - cy
    ull dn = fma2(e, e, C01);
    float2 d = upk(dn);
    float2 rc;
    rc.x = frcp_a(d.x);
    rc.y = frcp_a(d.y);
    return rc;
}

template<bool BORDER>
__device__ __forceinline__ float census_body(const float* __restrict__ sx,
                                             const float* __restrict__ sy,
                                             int ty, int tx, int r, int c0)
{
    const ull NEG1 = pk(-1.f, -1.f);
    const ull C729 = pk(7.29f, 7.29f);
    const ull C01  = pk(0.1f, 0.1f);

    float vrow[4], vcw[8];
    float va0 = 0.f, va1 = 0.f;
    if (BORDER) {
#pragma unroll
        for (int d = 0; d < 4; d++) vrow[d] = ((unsigned)(r + d - 3) < 250u) ? 1.f : 0.f;
#pragma unroll
        for (int j = 0; j < 8; j++) vcw[j] = ((unsigned)(c0 - 6 + j) < 250u) ? 1.f : 0.f;  // j-3 -> dx+... j maps dx=j-3? see use
        va0 = vrow[0] * vcw[3];
        va1 = vrow[0] * vcw[4];
    }

    // base float offset of float2 index 'tx' in row (ty+3+dy)
    const int rowoff0 = (ty + 3) * SW + 2 * tx;

    float accA = 0.f, accB = 0.f, accw = 0.f;

    // ---- center row (dy = 0): u2 holds the two centers (aligned) ----
    ull cenx, ceny;
    {
        const float* px = sx + rowoff0;
        const float* py = sy + rowoff0;
        ull ux2 = lds64(px + 4), ux3 = lds64(px + 6), ux4 = lds64(px + 8);
        ull uy2 = lds64(py + 4), uy3 = lds64(py + 6), uy4 = lds64(py + 8);
        cenx = ux2; ceny = uy2;
        float2 x2 = upk(ux2), x3 = upk(ux3), x4 = upk(ux4);
        float2 y2 = upk(uy2), y3 = upk(uy3), y4 = upk(uy4);

        // dx=1 (odd): pk halves; dx=2: aligned u3; dx=3: pk halves
        {
            float2 rc = pair_rc2(pk(x2.y, x3.x), pk(y2.y, y3.x), cenx, ceny, NEG1, C729, C01);
            if (BORDER) { float w0 = fmaf(vrow[0], vcw[4], va0), w1 = fmaf(vrow[0], vcw[5], va1);
                          accw += w0 + w1; accA = fmaf(w0, rc.x, accA); accB = fmaf(w1, rc.y, accB); }
            else { accA += rc.x; accB += rc.y; }
        }
        {
            float2 rc = pair_rc2(ux3, uy3, cenx, ceny, NEG1, C729, C01);
            if (BORDER) { float w0 = fmaf(vrow[0], vcw[5], va0), w1 = fmaf(vrow[0], vcw[6], va1);
                          accw += w0 + w1; accA = fmaf(w0, rc.x, accA); accB = fmaf(w1, rc.y, accB); }
            else { accA += rc.x; accB += rc.y; }
        }
        {
            float2 rc = pair_rc2(pk(x3.y, x4.x), pk(y3.y, y4.x), cenx, ceny, NEG1, C729, C01);
            if (BORDER) { float w0 = fmaf(vrow[0], vcw[6], va0), w1 = fmaf(vrow[0], vcw[7], va1);
                          accw += w0 + w1; accA = fmaf(w0, rc.x, accA); accB = fmaf(w1, rc.y, accB); }
            else { accA += rc.x; accB += rc.y; }
        }
    }

    // ---- dy = 1..3: dx = -3..3 ----
#pragma unroll
    for (int dy = 1; dy < 4; dy++) {
        const float* px = sx + rowoff0 + dy * SW;
        const float* py = sy + rowoff0 + dy * SW;
        ull ux0 = lds64(px), ux1 = lds64(px + 2), ux2 = lds64(px + 4), ux3 = lds64(px + 6), ux4 = lds64(px + 8);
        ull uy0 = lds64(py), uy1 = lds64(py + 2), uy2 = lds64(py + 4), uy3 = lds64(py + 6), uy4 = lds64(py + 8);
        float2 x0 = upk(ux0), x1 = upk(ux1), x2 = upk(ux2), x3 = upk(ux3), x4 = upk(ux4);
        float2 y0 = upk(uy0), y1 = upk(uy1), y2 = upk(uy2), y3 = upk(uy3), y4 = upk(uy4);

        // neighbor pair regs for dx = -3..3 ; aligned for even dx
        ull nx[7], ny[7];
        nx[0] = pk(x0.y, x1.x);  ny[0] = pk(y0.y, y1.x);   // dx=-3
        nx[1] = ux1;             ny[1] = uy1;              // dx=-2
        nx[2] = pk(x1.y, x2.x);  ny[2] = pk(y1.y, y2.x);   // dx=-1
        nx[3] = ux2;             ny[3] = uy2;              // dx= 0
        nx[4] = pk(x2.y, x3.x);  ny[4] = pk(y2.y, y3.x);   // dx=+1
        nx[5] = ux3;             ny[5] = uy3;              // dx=+2
        nx[6] = pk(x3.y, x4.x);  ny[6] = pk(y3.y, y4.x);   // dx=+3

#pragma unroll
        for (int j = 0; j < 7; j++) {
            float2 rc = pair_rc2(nx[j], ny[j], cenx, ceny, NEG1, C729, C01);
            if (BORDER) {
                float w0 = fmaf(vrow[dy], vcw[j], va0);
                float w1 = fmaf(vrow[dy], vcw[j + 1], va1);
                accw += w0 + w1;
                accA = fmaf(w0, rc.x, accA);
                accB = fmaf(w1, rc.y, accB);
            } else {
                accA += rc.x;
                accB += rc.y;
            }
        }
    }

    float s = accA + accB;
    return BORDER ? fmaf(-0.1f, s, accw) : fmaf(-0.2f, s, 96.f);
}

__global__ __launch_bounds__(256, 4)
void census_loss_kernel(const float* __restrict__ x,
                        const float* __restrict__ y,
                        float* __restrict__ out)
{
    __shared__ __align__(16) float sgx[SWR * SW];
    __shared__ __align__(16) float sgy[SWR * SW];

    const int b    = blockIdx.z;
    const int row0 = blockIdx.y * TROWS;
    const int col0 = blockIdx.x * TCOLS;
    const int tid  = threadIdx.y * 16 + threadIdx.x;

    const float* xb = x + (size_t)b * 3 * IMG2;
    const float* yb = y + (size_t)b * 3 * IMG2;

    // 3*grayscale tile + halo (left halo 4; zeros outside image)
    for (int i = tid; i < SWR * SW; i += 256) {
        int lr = i / SW;
        int lc = i - lr * SW;
        int gr = row0 - 3 + lr;
        int gc = col0 - 4 + lc;
        float gx = 0.f, gy = 0.f;
        if ((unsigned)gr < 256u && (unsigned)gc < 256u) {
            int o = gr * IMG + gc;
            gx = xb[o] + xb[o + IMG2] + xb[o + 2 * IMG2];
            gy = yb[o] + yb[o + IMG2] + yb[o + 2 * IMG2];
        }
        sgx[i] = gx;
        sgy[i] = gy;
    }
    __syncthreads();

    const int tx = threadIdx.x;          // 0..15 -> pixel cols 2tx, 2tx+1
    const int ty = threadIdx.y;          // 0..15 -> pixel row
    const int r  = row0 + ty;
    const int c0 = col0 + 2 * tx;

    const bool interior = (blockIdx.x - 1u < 6u) & (blockIdx.y - 1u < 14u);

    float acc = interior ? census_body<false>(sgx, sgy, ty, tx, r, c0)
                         : census_body<true >(sgx, sgy, ty, tx, r, c0);

    // warp + block reduction
#pragma unroll
    for (int s = 16; s > 0; s >>= 1)
        acc += __shfl_xor_sync(0xFFFFFFFFu, acc, s);

    __shared__ float wsum[8];
    if ((tid & 31) == 0) wsum[tid >> 5] = acc;
    __syncthreads();
    if (tid < 8) {
        float v = wsum[tid];
        v += __shfl_xor_sync(0xFFu, v, 4);
        v += __shfl_xor_sync(0xFFu, v, 2);
        v += __shfl_xor_sync(0xFFu, v, 1);
        if (tid == 0)
            atomicAdd(out, v * (1.f / 25690112.f));   // 1/(49*8*256*256)
    }
}

extern "C" void kernel_launch(void* const* d_in, const int* in_sizes, int n_in,
                              void* d_out, int out_size)
{
    const float* x = (const float*)d_in[0];
    const float* y = (const float*)d_in[1];
    float* out = (float*)d_out;

    cudaMemsetAsync(out, 0, sizeof(float));

    dim3 block(16, 16, 1);
    dim3 grid(IMG / TCOLS, IMG / TROWS, 8);   // 8 x 16 x 8 = 1024 blocks
    census_loss_kernel<<<grid, block>>>(x, y, out);
}